// round 2
// baseline (speedup 1.0000x reference)
#include <cuda_runtime.h>
#include <cstdint>

// GestureRNN: 2-layer ReLU RNN, B=4096, T=512, IN=10, H=32, NCLS=9.
// Warp-per-batch, lane j owns hidden unit j, weights in registers as f32x2.
// R1 changes vs R0:
//  - software pipeline: the 8 LDS of h1_new feed BOTH layer-1 (wi1) and the
//    NEXT step's layer-0 partial (w0)  -> 8 fewer LDS/step
//  - double-buffered h2 -> 2 syncwarps/step instead of 4
//  - h2_old loads + wh1 FMAs hoisted before the h1-publication sync
//  - 4 accumulator chains in layer 1 for shorter dependent chains

typedef unsigned long long ull;

__device__ __forceinline__ ull ffma2(ull a, ull b, ull c) {
    ull d;
    asm("fma.rn.f32x2 %0, %1, %2, %3;" : "=l"(d) : "l"(a), "l"(b), "l"(c));
    return d;
}
__device__ __forceinline__ ull fadd2(ull a, ull b) {
    ull d;
    asm("add.rn.f32x2 %0, %1, %2;" : "=l"(d) : "l"(a), "l"(b));
    return d;
}
__device__ __forceinline__ float hsum2(ull a) {
    return __uint_as_float((unsigned)a) + __uint_as_float((unsigned)(a >> 32));
}

static constexpr int T_STEPS = 512;
static constexpr int BATCH   = 4096;
static constexpr int IN_DIM  = 10;
static constexpr int NCLS    = 9;
static constexpr int WARPS   = 4;

struct __align__(16) WarpBuf {
    float x[12];       // x[10..11] stay 0
    float h1[32];
    float h2[2][32];   // double buffer
};

__global__ void __launch_bounds__(WARPS * 32, 3) rnn_fused_kernel(
    const float* __restrict__ x,
    const float* __restrict__ Wih0, const float* __restrict__ Whh0,
    const float* __restrict__ bih0, const float* __restrict__ bhh0,
    const float* __restrict__ Wih1, const float* __restrict__ Whh1,
    const float* __restrict__ bih1, const float* __restrict__ bhh1,
    const float* __restrict__ Wfc,  const float* __restrict__ bfc,
    float* __restrict__ out)
{
    __shared__ WarpBuf buf[WARPS];

    const int w   = threadIdx.x >> 5;
    const int lid = threadIdx.x & 31;
    const int b   = blockIdx.x * WARPS + w;
    WarpBuf& wb = buf[w];

    // ---- per-lane weight rows, packed f32x2 ----
    ull w0[16], wi1[16], wh1[16], wx[5];
    {
        const ulonglong2* p0 = (const ulonglong2*)(Whh0 + lid * 32);
        const ulonglong2* p1 = (const ulonglong2*)(Wih1 + lid * 32);
        const ulonglong2* p2 = (const ulonglong2*)(Whh1 + lid * 32);
#pragma unroll
        for (int m = 0; m < 8; m++) {
            ulonglong2 a = p0[m]; w0[2*m]  = a.x; w0[2*m+1]  = a.y;
            ulonglong2 c = p1[m]; wi1[2*m] = c.x; wi1[2*m+1] = c.y;
            ulonglong2 d = p2[m]; wh1[2*m] = d.x; wh1[2*m+1] = d.y;
        }
        const ull* px = (const ull*)(Wih0 + lid * IN_DIM);
#pragma unroll
        for (int m = 0; m < 5; m++) wx[m] = px[m];
    }
    const float b0 = bih0[lid] + bhh0[lid];
    const float b1 = bih1[lid] + bhh1[lid];

    // ---- init ----
    wb.h2[0][lid] = 0.f;
    if (lid < 12) wb.x[lid] = 0.f;

    const float* xb = x + (size_t)b * (T_STEPS * IN_DIM);
    float rx = (lid < IN_DIM) ? xb[lid] : 0.f;   // x for t=0
    __syncwarp();

    const ulonglong2* xp  = (const ulonglong2*)wb.x;
    const ulonglong2* h1p = (const ulonglong2*)wb.h1;

    ull accA = 0ull, accB = 0ull;   // carried: sum_k h1_{t-1}[k] * w0 pairs

    for (int t = 0; t < T_STEPS; t++) {
        if (lid < IN_DIM) wb.x[lid] = rx;
        __syncwarp();   // publishes x_t; also covers prev-step h2 STS

        // prefetch next x early (latency fully hidden by this step)
        {
            int tn = (t + 1 < T_STEPS) ? (t + 1) : t;
            if (lid < IN_DIM) rx = xb[tn * IN_DIM + lid];
        }

        // ---- finish layer 0: xproj + carried w0·h1_{t-1} partial ----
        ulonglong2 q0 = xp[0];
        ulonglong2 q1 = xp[1];
        ull        xa = *(const ull*)(wb.x + 8);
        ull s0 = ffma2(wx[0], q0.x, accA);
        ull s1 = ffma2(wx[1], q0.y, accB);
        s0 = ffma2(wx[2], q1.x, s0);
        s1 = ffma2(wx[3], q1.y, s1);
        s0 = ffma2(wx[4], xa,   s0);
        float h1n = fmaxf(b0 + hsum2(fadd2(s0, s1)), 0.f);

        // ---- layer-1 h2_old part: independent of h1n, hides sync latency ----
        const ulonglong2* h2r = (const ulonglong2*)wb.h2[t & 1];
        ull aA = 0ull, aB = 0ull, aC = 0ull, aD = 0ull;
#pragma unroll
        for (int m = 0; m < 8; m += 2) {
            ulonglong2 r0 = h2r[m];
            ulonglong2 r1 = h2r[m + 1];
            aA = ffma2(wh1[2*m],     r0.x, aA);
            aB = ffma2(wh1[2*m+1],   r0.y, aB);
            aC = ffma2(wh1[2*m+2],   r1.x, aC);
            aD = ffma2(wh1[2*m+3],   r1.y, aD);
        }

        wb.h1[lid] = h1n;
        __syncwarp();   // publishes h1_t

        // ---- dual-use h1_t reads: wi1 (this step) + w0 (next step) ----
        ull nA = 0ull, nB = 0ull;
#pragma unroll
        for (int m = 0; m < 8; m += 2) {
            ulonglong2 q  = h1p[m];
            ulonglong2 q2 = h1p[m + 1];
            aA = ffma2(wi1[2*m],     q.x,  aA);
            aB = ffma2(wi1[2*m+1],   q.y,  aB);
            nA = ffma2(w0[2*m],      q.x,  nA);
            nB = ffma2(w0[2*m+1],    q.y,  nB);
            aC = ffma2(wi1[2*m+2],   q2.x, aC);
            aD = ffma2(wi1[2*m+3],   q2.y, aD);
            nA = ffma2(w0[2*m+2],    q2.x, nA);
            nB = ffma2(w0[2*m+3],    q2.y, nB);
        }
        float h2n = fmaxf(b1 + hsum2(fadd2(fadd2(aA, aB), fadd2(aC, aD))), 0.f);
        wb.h2[(t & 1) ^ 1][lid] = h2n;   // published by next iteration's sync

        accA = nA; accB = nB;
    }
    __syncwarp();

    // ---- classifier head on last h2 (t=511 wrote buffer 0) ----
    if (lid < NCLS) {
        float o = bfc[lid];
        const float* wr = Wfc + lid * 32;
        const float* h2f = wb.h2[0];
#pragma unroll
        for (int j = 0; j < 32; j++) o += h2f[j] * wr[j];
        out[(size_t)b * NCLS + lid] = o;
    }
}

extern "C" void kernel_launch(void* const* d_in, const int* in_sizes, int n_in,
                              void* d_out, int out_size)
{
    const float* x    = (const float*)d_in[0];
    const float* Wih0 = (const float*)d_in[1];
    const float* Whh0 = (const float*)d_in[2];
    const float* bih0 = (const float*)d_in[3];
    const float* bhh0 = (const float*)d_in[4];
    const float* Wih1 = (const float*)d_in[5];
    const float* Whh1 = (const float*)d_in[6];
    const float* bih1 = (const float*)d_in[7];
    const float* bhh1 = (const float*)d_in[8];
    const float* Wfc  = (const float*)d_in[9];
    const float* bfc  = (const float*)d_in[10];
    float* out = (float*)d_out;

    rnn_fused_kernel<<<BATCH / WARPS, WARPS * 32>>>(
        x, Wih0, Whh0, bih0, bhh0, Wih1, Whh1, bih1, bhh1, Wfc, bfc, out);
}

// round 4
// speedup vs baseline: 1.2918x; 1.2918x over previous
#include <cuda_runtime.h>
#include <cstdint>

// GestureRNN: 2-layer ReLU RNN, B=4096, T=512, IN=10, H=32, NCLS=9.
// R2: warp handles TWO batch elements (same weight regs, 2 independent
// dependency chains -> 2x ILP per scheduler). h1/h2 double-buffered ->
// 2 syncwarps/step. Plain R0-style FMA loops (no dual-use fusion).

typedef unsigned long long ull;

__device__ __forceinline__ ull ffma2(ull a, ull b, ull c) {
    ull d;
    asm("fma.rn.f32x2 %0, %1, %2, %3;" : "=l"(d) : "l"(a), "l"(b), "l"(c));
    return d;
}
__device__ __forceinline__ float hsum2(ull a) {
    return __uint_as_float((unsigned)a) + __uint_as_float((unsigned)(a >> 32));
}

static constexpr int T_STEPS = 512;
static constexpr int BATCH   = 4096;
static constexpr int IN_DIM  = 10;
static constexpr int NCLS    = 9;
static constexpr int WARPS   = 2;   // 64-thread CTAs

struct __align__(16) BatchBuf {
    float x[12];        // x[10..11] stay 0
    float h1[2][32];    // double buffer
    float h2[2][32];    // double buffer
};

__global__ void __launch_bounds__(WARPS * 32, 6) rnn_fused_kernel(
    const float* __restrict__ x,
    const float* __restrict__ Wih0, const float* __restrict__ Whh0,
    const float* __restrict__ bih0, const float* __restrict__ bhh0,
    const float* __restrict__ Wih1, const float* __restrict__ Whh1,
    const float* __restrict__ bih1, const float* __restrict__ bhh1,
    const float* __restrict__ Wfc,  const float* __restrict__ bfc,
    float* __restrict__ out)
{
    __shared__ BatchBuf buf[WARPS][2];

    const int w   = threadIdx.x >> 5;
    const int lid = threadIdx.x & 31;
    const int b0  = (blockIdx.x * WARPS + w) * 2;
    BatchBuf& B0 = buf[w][0];
    BatchBuf& B1 = buf[w][1];

    // ---- per-lane weight rows, packed f32x2 (shared by both batches) ----
    ull w0[16], wi1[16], wh1[16], wx[5];
    {
        const ulonglong2* p0 = (const ulonglong2*)(Whh0 + lid * 32);
        const ulonglong2* p1 = (const ulonglong2*)(Wih1 + lid * 32);
        const ulonglong2* p2 = (const ulonglong2*)(Whh1 + lid * 32);
#pragma unroll
        for (int m = 0; m < 8; m++) {
            ulonglong2 a = p0[m]; w0[2*m]  = a.x; w0[2*m+1]  = a.y;
            ulonglong2 c = p1[m]; wi1[2*m] = c.x; wi1[2*m+1] = c.y;
            ulonglong2 d = p2[m]; wh1[2*m] = d.x; wh1[2*m+1] = d.y;
        }
        const ull* px = (const ull*)(Wih0 + lid * IN_DIM);
#pragma unroll
        for (int m = 0; m < 5; m++) wx[m] = px[m];
    }
    const float bs0 = bih0[lid] + bhh0[lid];
    const float bs1 = bih1[lid] + bhh1[lid];

    // ---- init ----
    B0.h1[0][lid] = 0.f;  B1.h1[0][lid] = 0.f;
    B0.h2[0][lid] = 0.f;  B1.h2[0][lid] = 0.f;
    if (lid < 12) { B0.x[lid] = 0.f; B1.x[lid] = 0.f; }

    const float* xb0 = x + (size_t)(b0)     * (T_STEPS * IN_DIM);
    const float* xb1 = x + (size_t)(b0 + 1) * (T_STEPS * IN_DIM);
    float rx0 = (lid < IN_DIM) ? xb0[lid] : 0.f;
    float rx1 = (lid < IN_DIM) ? xb1[lid] : 0.f;
    __syncwarp();

    for (int t = 0; t < T_STEPS; t++) {
        const int p = t & 1;          // read buffer
        const int q = p ^ 1;          // write buffer

        if (lid < IN_DIM) { B0.x[lid] = rx0; B1.x[lid] = rx1; }
        __syncwarp();   // publishes x_t and prev step's h2 writes

        // prefetch next x
        {
            int tn = (t + 1 < T_STEPS) ? (t + 1) : t;
            if (lid < IN_DIM) {
                rx0 = xb0[tn * IN_DIM + lid];
                rx1 = xb1[tn * IN_DIM + lid];
            }
        }

        // ---- layer 0 for both batches ----
        const ulonglong2* x0p = (const ulonglong2*)B0.x;
        const ulonglong2* x1p = (const ulonglong2*)B1.x;
        ulonglong2 u0 = x0p[0], u1 = x0p[1];
        ulonglong2 v0 = x1p[0], v1 = x1p[1];
        ull ua = *(const ull*)(B0.x + 8);
        ull va = *(const ull*)(B1.x + 8);

        ull s0A = ffma2(wx[0], u0.x, (ull)0);
        ull s1A = ffma2(wx[0], v0.x, (ull)0);
        ull s0B = ffma2(wx[1], u0.y, (ull)0);
        ull s1B = ffma2(wx[1], v0.y, (ull)0);
        s0A = ffma2(wx[2], u1.x, s0A);
        s1A = ffma2(wx[2], v1.x, s1A);
        s0B = ffma2(wx[3], u1.y, s0B);
        s1B = ffma2(wx[3], v1.y, s1B);
        s0A = ffma2(wx[4], ua, s0A);
        s1A = ffma2(wx[4], va, s1A);

        const ulonglong2* h1r0 = (const ulonglong2*)B0.h1[p];
        const ulonglong2* h1r1 = (const ulonglong2*)B1.h1[p];
#pragma unroll
        for (int m = 0; m < 8; m++) {
            ulonglong2 qa = h1r0[m];
            ulonglong2 qb = h1r1[m];
            s0A = ffma2(w0[2*m],   qa.x, s0A);
            s1A = ffma2(w0[2*m],   qb.x, s1A);
            s0B = ffma2(w0[2*m+1], qa.y, s0B);
            s1B = ffma2(w0[2*m+1], qb.y, s1B);
        }
        float h1n0 = fmaxf(bs0 + hsum2(s0A) + hsum2(s0B), 0.f);
        float h1n1 = fmaxf(bs0 + hsum2(s1A) + hsum2(s1B), 0.f);
        B0.h1[q][lid] = h1n0;
        B1.h1[q][lid] = h1n1;
        __syncwarp();   // publishes h1_t

        // ---- layer 1 for both batches ----
        const ulonglong2* h1n0p = (const ulonglong2*)B0.h1[q];
        const ulonglong2* h1n1p = (const ulonglong2*)B1.h1[q];
        const ulonglong2* h2r0  = (const ulonglong2*)B0.h2[p];
        const ulonglong2* h2r1  = (const ulonglong2*)B1.h2[p];

        ull a0A = 0ull, a0B = 0ull, a1A = 0ull, a1B = 0ull;
#pragma unroll
        for (int m = 0; m < 8; m++) {
            ulonglong2 qa = h1n0p[m];
            ulonglong2 qb = h1n1p[m];
            a0A = ffma2(wi1[2*m],   qa.x, a0A);
            a1A = ffma2(wi1[2*m],   qb.x, a1A);
            a0B = ffma2(wi1[2*m+1], qa.y, a0B);
            a1B = ffma2(wi1[2*m+1], qb.y, a1B);
        }
#pragma unroll
        for (int m = 0; m < 8; m++) {
            ulonglong2 ra = h2r0[m];
            ulonglong2 rb = h2r1[m];
            a0A = ffma2(wh1[2*m],   ra.x, a0A);
            a1A = ffma2(wh1[2*m],   rb.x, a1A);
            a0B = ffma2(wh1[2*m+1], ra.y, a0B);
            a1B = ffma2(wh1[2*m+1], rb.y, a1B);
        }
        float h2n0 = fmaxf(bs1 + hsum2(a0A) + hsum2(a0B), 0.f);
        float h2n1 = fmaxf(bs1 + hsum2(a1A) + hsum2(a1B), 0.f);
        B0.h2[q][lid] = h2n0;     // published by next step's top sync
        B1.h2[q][lid] = h2n1;
    }
    __syncwarp();

    // ---- classifier head: final h2 is in buffer 0 (T even) ----
    if (lid < NCLS) {
        const float* wr = Wfc + lid * 32;
        float o0 = bfc[lid], o1 = bfc[lid];
        const float* f0 = B0.h2[0];
        const float* f1 = B1.h2[0];
#pragma unroll
        for (int j = 0; j < 32; j++) {
            o0 += f0[j] * wr[j];
            o1 += f1[j] * wr[j];
        }
        out[(size_t)(b0)     * NCLS + lid] = o0;
        out[(size_t)(b0 + 1) * NCLS + lid] = o1;
    }
}

extern "C" void kernel_launch(void* const* d_in, const int* in_sizes, int n_in,
                              void* d_out, int out_size)
{
    const float* x    = (const float*)d_in[0];
    const float* Wih0 = (const float*)d_in[1];
    const float* Whh0 = (const float*)d_in[2];
    const float* bih0 = (const float*)d_in[3];
    const float* bhh0 = (const float*)d_in[4];
    const float* Wih1 = (const float*)d_in[5];
    const float* Whh1 = (const float*)d_in[6];
    const float* bih1 = (const float*)d_in[7];
    const float* bhh1 = (const float*)d_in[8];
    const float* Wfc  = (const float*)d_in[9];
    const float* bfc  = (const float*)d_in[10];
    float* out = (float*)d_out;

    rnn_fused_kernel<<<BATCH / (WARPS * 2), WARPS * 32>>>(
        x, Wih0, Whh0, bih0, bhh0, Wih1, Whh1, bih1, bhh1, Wfc, bfc, out);
}